// round 11
// baseline (speedup 1.0000x reference)
#include <cuda_runtime.h>

#define H 512
#define W 512
#define NPTS 12
#define NMAPS 16          // B(8) * 2 groups
#define TSAT 21.0f        // d >= TSAT -> tanh(2*sqrt(d)) == 1.0f exactly in fp32

// tanh(2*sqrt(d)) = 1 - 2/(exp(4*sqrt(d)) + 1); only called with d < TSAT.
__device__ __forceinline__ float fast_out(float d) {
    float s, t, r;
    asm("sqrt.approx.f32 %0, %1;" : "=f"(s) : "f"(d));
    float e = 5.770780163555852f * s;          // 4*log2(e)*sqrt(d)
    asm("ex2.approx.f32 %0, %1;" : "=f"(t) : "f"(e));
    float tp1 = t + 1.0f;
    asm("rcp.approx.f32 %0, %1;" : "=f"(r) : "f"(tp1));
    return fmaf(-2.0f, r, 1.0f);
}

// Block = (map, 4 rows). 2048 blocks x 256 threads (8 warps), 2 float4/thread.
// NO __syncthreads anywhere. Each warp is autonomous:
//   1. store 1.0f to both of its float4s immediately (no dependencies)
//   2. lanes 0-11 LDG the 12 points; STS to smem (all warps write IDENTICAL
//      values -> benign race); __syncwarp
//   3. warp builds ONLY its own 32-bit coverage word via redux.or
//   4. covered lanes (~3%) recompute exact min+tanh (scalar, register-lean)
//      and overwrite their OWN float4s (same-thread order => patch wins)
__global__ __launch_bounds__(256, 8) void distmaps_kernel(
    const float* __restrict__ coords,   // (8, 24, 3)
    float* __restrict__ out)            // (8, 2, 512, 512)
{
    const int b    = blockIdx.x;
    const int m    = b >> 7;            // map 0..15
    const int r0   = (b & 127) * 4;     // first of 4 rows
    const int tid  = threadIdx.x;
    const int lane = tid & 31;
    const int ri   = tid >> 7;          // 0/1
    const int c4   = tid & 127;         // float4 column 0..127
    const int rA   = r0 + ri;
    const int rB   = r0 + ri + 2;

    __shared__ float sp_y[NPTS];
    __shared__ float sp_nx[NPTS];       // -x * 0.2
    __shared__ float sp_base[NPTS];     // 0 valid, 1e6 invalid

    // ---- Phase 1: unconditional stores (the bulk of the output) ----
    const float4 one = make_float4(1.0f, 1.0f, 1.0f, 1.0f);
    float4* pA = (float4*)(out + ((size_t)m * H + rA) * W) + c4;
    float4* pB = (float4*)(out + ((size_t)m * H + rB) * W) + c4;
    *pA = one;
    *pB = one;

    // ---- Phase 2: per-warp mask word (no block barrier) ----
    unsigned wbit = 0;
    if (lane < NPTS) {
        const float* q = coords + (m * NPTS + lane) * 3;
        float y = q[0];
        float x = q[1];
        bool valid = fmaxf(y, x) >= 0.0f;
        sp_y[lane]    = y;
        sp_nx[lane]   = -x * 0.2f;
        sp_base[lane] = valid ? 0.0f : 1000000.0f;
        if (valid) {
            // nearest integer row within the 4-row band (convex in r)
            float rn = rintf(fminf(fmaxf(y, (float)r0), (float)(r0 + 3)));
            float dr = (rn - y) * 0.2f;
            if (dr * dr < TSAT) {
                int fb = (((int)floorf(x) - 23) & ~3) >> 2;  // first f4 col
                int lo = max(fb, 0);
                int hi = min(fb + 12, 127);
                // this warp's 32-column word: [32*(c4>>5), +31]
                int w  = (c4 >> 5);                           // warp-uniform
                int l  = max(lo - 32 * w, 0);
                int h  = min(hi - 32 * w, 31);
                if (h >= 0 && l <= 31 && l <= h) {
                    wbit = ((h == 31) ? 0xFFFFFFFFu : ((1u << (h + 1)) - 1u))
                           & ~((1u << l) - 1u);
                }
            }
        }
    }
    __syncwarp();
    unsigned word = __reduce_or_sync(0xffffffffu, wbit);

    // ---- Phase 3: covered lanes overwrite with exact values ----
    if ((word >> (c4 & 31)) & 1u) {
        const float cs0 = (float)(c4 * 4)     * 0.2f;
        const float cs1 = (float)(c4 * 4 + 1) * 0.2f;
        const float cs2 = (float)(c4 * 4 + 2) * 0.2f;
        const float cs3 = (float)(c4 * 4 + 3) * 0.2f;

#pragma unroll
        for (int half = 0; half < 2; half++) {
            const float rf = (float)(half ? rB : rA);
            float m0 = 1.0e6f, m1 = 1.0e6f, m2 = 1.0e6f, m3 = 1.0e6f;
#pragma unroll
            for (int j = 0; j < NPTS; j++) {
                float t = (rf - sp_y[j]) * 0.2f;
                float a = fmaf(t, t, sp_base[j]);
                float nx = sp_nx[j];
                float d0 = cs0 + nx, d1 = cs1 + nx, d2 = cs2 + nx, d3 = cs3 + nx;
                m0 = fminf(m0, fmaf(d0, d0, a));
                m1 = fminf(m1, fmaf(d1, d1, a));
                m2 = fminf(m2, fmaf(d2, d2, a));
                m3 = fminf(m3, fmaf(d3, d3, a));
            }
            float4 v;
            v.x = (m0 < TSAT) ? fast_out(m0) : 1.0f;
            v.y = (m1 < TSAT) ? fast_out(m1) : 1.0f;
            v.z = (m2 < TSAT) ? fast_out(m2) : 1.0f;
            v.w = (m3 < TSAT) ? fast_out(m3) : 1.0f;
            if (half) *pB = v; else *pA = v;
        }
    }
}

extern "C" void kernel_launch(void* const* d_in, const int* in_sizes, int n_in,
                              void* d_out, int out_size)
{
    const float* coords = nullptr;
    for (int i = 0; i < n_in; i++) {
        if (in_sizes[i] == 8 * 24 * 3) { coords = (const float*)d_in[i]; break; }
    }
    if (!coords) coords = (const float*)d_in[n_in - 1];

    float* out = (float*)d_out;

    distmaps_kernel<<<NMAPS * 128, 256>>>(coords, out);
}

// round 12
// speedup vs baseline: 1.3689x; 1.3689x over previous
#include <cuda_runtime.h>

#define H 512
#define W 512
#define NPTS 12
#define NMAPS 16          // B(8) * 2 groups
#define TSAT 21.0f        // d >= TSAT -> tanh(2*sqrt(d)) == 1.0f exactly in fp32
#define PCOL4 13          // float4 columns per patch window

// tanh(2*sqrt(d)) = 1 - 2/(exp(4*sqrt(d)) + 1); only called with d < TSAT.
__device__ __forceinline__ float fast_out(float d) {
    float s, t, r;
    asm("sqrt.approx.f32 %0, %1;" : "=f"(s) : "f"(d));
    float e = 5.770780163555852f * s;          // 4*log2(e)*sqrt(d)
    asm("ex2.approx.f32 %0, %1;" : "=f"(t) : "f"(e));
    float tp1 = t + 1.0f;
    asm("rcp.approx.f32 %0, %1;" : "=f"(r) : "f"(tp1));
    return fmaf(-2.0f, r, 1.0f);
}

// ---- Kernel 1: pure fill. 2048 blocks x 256 threads, 2 float4/thread.
// Zero dependencies -> measured ~4.3us. Block 0 additionally prefetches the
// 2.3KB coords into L2 so the patch kernel's load hits L2, not DRAM.
__global__ __launch_bounds__(256) void fill_kernel(
    float4* __restrict__ out, const float4* __restrict__ coords4)
{
    const float4 one = make_float4(1.0f, 1.0f, 1.0f, 1.0f);
    unsigned idx = blockIdx.x * 512u + threadIdx.x;
    out[idx]       = one;
    out[idx + 256] = one;
    if (blockIdx.x == 0 && threadIdx.x < (NMAPS * NPTS * 3 + 3) / 4) {
        float4 v = __ldg(coords4 + threadIdx.x);
        if (v.x < -1.0e30f) ((float*)out)[0] = v.y;   // never taken; keeps the load
    }
}

// ---- Kernel 2: patch. 384 blocks (2 per (map,point)) x 256 threads.
// Single 9-float4 LDG for the map's coords (L2-hot), <=2 units/thread,
// full 12-point exact min per pixel (overlap writes byte-identical).
__global__ __launch_bounds__(256) void patch_kernel(
    const float4* __restrict__ coords4,   // (8,24,3) viewed as float4[144]
    float* __restrict__ out)              // (8, 2, 512, 512)
{
    const int blk  = blockIdx.x;
    const int m    = blk / 24;            // map 0..15
    const int rem  = blk - m * 24;
    const int p    = rem >> 1;            // point 0..11
    const int half = rem & 1;
    const int tid  = threadIdx.x;

    __shared__ float sc[36];              // this map's 12 x (y,x,z)

    if (tid < 9) {
        float4 v = __ldg(coords4 + m * 9 + tid);   // 36 floats per map
        ((float4*)sc)[tid] = v;
    }
    __syncthreads();

    const float yp = sc[p * 3 + 0];
    const float xp = sc[p * 3 + 1];
    if (fmaxf(yp, xp) < 0.0f) return;     // invalid anchor: no patch

    const int iy = (int)floorf(yp);
    const int ix = (int)floorf(xp);
    const int rbeg  = iy - 23 + half * 24;
    const int nrows = half ? 23 : 24;
    const int cb    = (ix - 23) & ~3;     // float4-aligned window start
    const int units = nrows * PCOL4;      // <= 312

    for (int u = tid; u < units; u += 256) {
        const int r = rbeg + u / PCOL4;
        const int c = cb + (u % PCOL4) * 4;
        if (r < 0 || r >= H || c < 0 || c > W - 4) continue;

        const float rf  = (float)r;
        const float cs0 = (float)c * 0.2f;
        const float cs1 = (float)(c + 1) * 0.2f;
        const float cs2 = (float)(c + 2) * 0.2f;
        const float cs3 = (float)(c + 3) * 0.2f;

        float m0 = 1.0e6f, m1 = 1.0e6f, m2 = 1.0e6f, m3 = 1.0e6f;
#pragma unroll
        for (int j = 0; j < NPTS; j++) {
            float y = sc[j * 3 + 0];
            float x = sc[j * 3 + 1];
            float base = (fmaxf(y, x) < 0.0f) ? 1000000.0f : 0.0f;
            float t = (rf - y) * 0.2f;
            float a = fmaf(t, t, base);
            float nx = -x * 0.2f;
            float d0 = cs0 + nx, d1 = cs1 + nx, d2 = cs2 + nx, d3 = cs3 + nx;
            m0 = fminf(m0, fmaf(d0, d0, a));
            m1 = fminf(m1, fmaf(d1, d1, a));
            m2 = fminf(m2, fmaf(d2, d2, a));
            m3 = fminf(m3, fmaf(d3, d3, a));
        }

        float4 v;
        v.x = (m0 < TSAT) ? fast_out(m0) : 1.0f;
        v.y = (m1 < TSAT) ? fast_out(m1) : 1.0f;
        v.z = (m2 < TSAT) ? fast_out(m2) : 1.0f;
        v.w = (m3 < TSAT) ? fast_out(m3) : 1.0f;

        *(float4*)(out + ((size_t)m * H + r) * W + c) = v;
    }
}

extern "C" void kernel_launch(void* const* d_in, const int* in_sizes, int n_in,
                              void* d_out, int out_size)
{
    const float* coords = nullptr;
    for (int i = 0; i < n_in; i++) {
        if (in_sizes[i] == 8 * 24 * 3) { coords = (const float*)d_in[i]; break; }
    }
    if (!coords) coords = (const float*)d_in[n_in - 1];

    float* out = (float*)d_out;

    fill_kernel<<<2048, 256>>>((float4*)out, (const float4*)coords);
    patch_kernel<<<NMAPS * NPTS * 2, 256>>>((const float4*)coords, out);
}